// round 14
// baseline (speedup 1.0000x reference)
#include <cuda_runtime.h>
#include <math.h>

#define D 128
#define MAXN 50048
#define MAXE 600064
#define TM 32                      // rows per tile
#define SROW 257                   // tile-buffer row stride (257 % 32 == 1)
#define FUSED_SMEM ((256*128 + 2*TM*SROW) * 4)   // 196,864 B
#define NTHREADS 384               // wid 0-7 producers, wid 8-11 compute

// ---------------- device scratch (no allocations allowed) ----------------
__device__ float g_bufA[(size_t)MAXN * D];
__device__ float g_bufB[(size_t)MAXN * D];
__device__ int   g_deg[MAXN];
__device__ int   g_off[MAXN + 1];
__device__ int   g_cursor[MAXN];
__device__ int   g_csr[MAXE];
__device__ int   g_bsum[256];
__device__ float g_invdeg[MAXN];

// buffer selectors: 0 = external pointer, 1 = g_bufA, 2 = g_bufB
static __device__ __forceinline__ const float* sel_src(const float* ext, int s) {
    return (s == 0) ? ext : ((s == 1) ? g_bufA : g_bufB);
}
static __device__ __forceinline__ float* sel_dst(float* ext, int s) {
    return (s == 0) ? ext : ((s == 1) ? g_bufA : g_bufB);
}

// ---------------- packed f32x2 helpers (FFMA2: 2x fp32 FMA throughput) ----
static __device__ __forceinline__ unsigned long long pk2(float x) {
    unsigned long long r;
    asm("mov.b64 %0, {%1, %1};" : "=l"(r) : "f"(x));
    return r;
}
static __device__ __forceinline__ void ffma2(unsigned long long& d,
                                             unsigned long long a,
                                             unsigned long long b) {
    asm("fma.rn.f32x2 %0, %1, %2, %0;" : "+l"(d) : "l"(a), "l"(b));
}
static __device__ __forceinline__ float2 upk(unsigned long long v) {
    float2 r;
    asm("mov.b64 {%0, %1}, %2;" : "=f"(r.x), "=f"(r.y) : "l"(v));
    return r;
}

// ---------------- CSR build (5 launches so fused kernel is launch #6) -----
__global__ void zero_deg_kernel(int n) {
    int i = blockIdx.x * blockDim.x + threadIdx.x;
    if (i < n) g_deg[i] = 0;
}

__global__ void count_kernel(const int* __restrict__ dst, int e) {
    int i = blockIdx.x * blockDim.x + threadIdx.x;
    if (i < e) atomicAdd(&g_deg[dst[i]], 1);
}

// per-512-block exclusive scan over degrees; also emits inv_deg = 1/max(deg,1)
__global__ void scan_block_kernel(int n) {
    __shared__ int s[512];
    int t = threadIdx.x;
    int i = blockIdx.x * 512 + t;
    int v = (i < n) ? g_deg[i] : 0;
    if (i < n) g_invdeg[i] = 1.0f / fmaxf((float)v, 1.0f);
    s[t] = v;
    __syncthreads();
    #pragma unroll
    for (int d = 1; d < 512; d <<= 1) {
        int x = (t >= d) ? s[t - d] : 0;
        __syncthreads();
        s[t] += x;
        __syncthreads();
    }
    if (i < n) g_off[i] = s[t] - v;
    if (t == 511) g_bsum[blockIdx.x] = s[511];
}

// merged spine-scan + add: every block redundantly scans the (<=128) block
// sums in smem (cheap), then applies the exclusive spine offset.
__global__ void scan_add_spine_kernel(int n, int e, int nb) {
    __shared__ int s[128];
    __shared__ int orig[128];
    int t = threadIdx.x;          // 512 threads
    if (t < 128) {
        int v = (t < nb) ? g_bsum[t] : 0;
        orig[t] = v;
        s[t] = v;
    }
    __syncthreads();
    #pragma unroll
    for (int d = 1; d < 128; d <<= 1) {
        int x = (t < 128 && t >= d) ? s[t - d] : 0;
        __syncthreads();
        if (t < 128) s[t] += x;
        __syncthreads();
    }
    int i = blockIdx.x * blockDim.x + t;
    if (i < n) {
        int o = g_off[i] + (s[i >> 9] - orig[i >> 9]);   // exclusive spine
        g_off[i] = o;
        g_cursor[i] = o;
    } else if (i == n) {
        g_off[n] = e;
    }
}

__global__ void fill_kernel(const int* __restrict__ src, const int* __restrict__ dst, int e) {
    int i = blockIdx.x * blockDim.x + threadIdx.x;
    if (i < e) {
        int d = dst[i];
        int p = atomicAdd(&g_cursor[d], 1);
        g_csr[p] = src[i];
    }
}

// ---------------- producer: build rows of a 32-row tile in SMEM ------------
// buf layout: buf[m*SROW + k], k in [0,128) = mean-aggregated neighbors,
//             k in [128,256) = X row (root term).
// 8 producer warps (wid 0-7), 4 rows each; all 4 rows advance together,
// 16 gathers in flight with next index group prefetched concurrently.
static __device__ __forceinline__ void produce_tile(
    float* __restrict__ buf, const float4* __restrict__ X4,
    int tile, int n, int pw, int lane)
{
    int base = tile * TM + pw * 4;

    int kk[4], ee[4];
    float4 acc[4], xv[4];
    #pragma unroll
    for (int i = 0; i < 4; i++) {
        int row = base + i;
        if (row < n) {
            kk[i] = __ldg(&g_off[row]);
            ee[i] = __ldg(&g_off[row + 1]);
            xv[i] = __ldg(&X4[(size_t)row * 32 + lane]);   // root term, early
        } else {
            kk[i] = 0; ee[i] = 0;
            xv[i] = make_float4(0.f, 0.f, 0.f, 0.f);
        }
        acc[i] = make_float4(0.f, 0.f, 0.f, 0.f);
    }

    int jc[16];
    #pragma unroll
    for (int i = 0; i < 4; i++)
        #pragma unroll
        for (int s = 0; s < 4; s++) {
            int pos = kk[i] + s;
            jc[i * 4 + s] = (pos < ee[i]) ? __ldg(&g_csr[pos]) : -1;
        }

    for (;;) {
        int more = 0;
        #pragma unroll
        for (int i = 0; i < 4; i++) more |= (kk[i] + 4 < ee[i]);

        int jn[16];
        #pragma unroll
        for (int i = 0; i < 4; i++)
            #pragma unroll
            for (int s = 0; s < 4; s++) {
                int pos = kk[i] + 4 + s;
                jn[i * 4 + s] = (more && pos < ee[i]) ? __ldg(&g_csr[pos]) : -1;
            }

        #pragma unroll
        for (int i = 0; i < 4; i++)
            #pragma unroll
            for (int s = 0; s < 4; s++) {
                int jj = jc[i * 4 + s];
                if (jj >= 0) {
                    float4 v = __ldg(&X4[(size_t)jj * 32 + lane]);
                    acc[i].x += v.x; acc[i].y += v.y;
                    acc[i].z += v.z; acc[i].w += v.w;
                }
            }

        #pragma unroll
        for (int i = 0; i < 4; i++) kk[i] += 4;
        if (!more) break;
        #pragma unroll
        for (int s = 0; s < 16; s++) jc[s] = jn[s];
    }

    #pragma unroll
    for (int i = 0; i < 4; i++) {
        int row = base + i;
        if (row < n) {
            float sc = __ldg(&g_invdeg[row]);
            float* bp = buf + (pw * 4 + i) * SROW + 4 * lane;
            bp[0] = acc[i].x * sc;
            bp[1] = acc[i].y * sc;
            bp[2] = acc[i].z * sc;
            bp[3] = acc[i].w * sc;
            bp[128 + 0] = xv[i].x;
            bp[128 + 1] = xv[i].y;
            bp[128 + 2] = xv[i].z;
            bp[128 + 3] = xv[i].w;
        }
    }
}

// ---------------- fused persistent kernel -------------------------------
// Y = ELU( mean_agg(X) @ W1 + X @ W2 + b )
// 12 warps: wid 0-7 producers (gather next tile), wid 8-11 compute.
// Compute warps have the HIGHEST wids -> arbiter priority protects the
// saturated FFMA2 pipe. 1 compute warp per SMSP: 28 issues/k vs 32 slots.
__global__ __launch_bounds__(NTHREADS, 1) void fused_layer_kernel(
    const float* __restrict__ Xext, int xsel,
    const float* __restrict__ W1, const float* __restrict__ W2,
    const float* __restrict__ bias,
    float* __restrict__ Yext, int ysel, int n, int ntiles)
{
    extern __shared__ float smem[];
    float* sW  = smem;                 // [256][128] : k<128 -> W1, else W2
    float* sB0 = smem + 256 * 128;
    float* sB1 = sB0 + TM * SROW;

    const float* X = sel_src(Xext, xsel);
    float* Y = sel_dst(Yext, ysel);
    const float4* X4 = (const float4*)X;

    int t    = threadIdx.x;
    int wid  = t >> 5;
    int lane = t & 31;
    bool is_comp = (wid >= 8);

    int mrow = 0, ncol = 0;
    float b[8];

    if (is_comp) {
        // ---- weight load ONCE by compute threads (ct = 0..127) ----
        int ct = t - 256;
        const float4* W1v = (const float4*)W1;
        const float4* W2v = (const float4*)W2;
        float4* sWv = (float4*)sW;
        #pragma unroll
        for (int i = 0; i < 32; i++) {
            int idx = ct + i * 128;            // 0..4095
            sWv[idx]        = __ldg(&W1v[idx]);
            sWv[idx + 4096] = __ldg(&W2v[idx]);
        }
        mrow = (ct & 7) * 4;                   // 4 rows
        ncol = (ct >> 3) * 8;                  // 8 cols = 4 f32x2 pairs
        #pragma unroll
        for (int j = 0; j < 8; j++) b[j] = __ldg(&bias[ncol + j]);
    } else {
        // ---- producers fill buffer 0 with the first tile meanwhile ----
        produce_tile(sB0, X4, blockIdx.x, n, wid, lane);
    }
    __syncthreads();

    int p = 0;
    for (int tile = blockIdx.x; tile < ntiles; tile += gridDim.x) {
        float* cur = p ? sB1 : sB0;
        float* nxt = p ? sB0 : sB1;

        if (is_comp) {
            // ---- FFMA2 main loop over K=256, 4 rows x 8 cols ----
            unsigned long long acc[4][4];
            #pragma unroll
            for (int r = 0; r < 4; r++)
                #pragma unroll
                for (int c = 0; c < 4; c++) acc[r][c] = 0ull;

            const float* ap = cur + mrow * SROW;
            const unsigned long long* wp = (const unsigned long long*)(sW + ncol);

            #pragma unroll 4
            for (int k = 0; k < 256; k++) {
                unsigned long long A0 = pk2(ap[k]);
                unsigned long long A1 = pk2(ap[k + SROW]);
                unsigned long long A2 = pk2(ap[k + 2 * SROW]);
                unsigned long long A3 = pk2(ap[k + 3 * SROW]);
                unsigned long long w0 = wp[0], w1 = wp[1],
                                   w2 = wp[2], w3 = wp[3];
                ffma2(acc[0][0], A0, w0); ffma2(acc[0][1], A0, w1);
                ffma2(acc[0][2], A0, w2); ffma2(acc[0][3], A0, w3);
                ffma2(acc[1][0], A1, w0); ffma2(acc[1][1], A1, w1);
                ffma2(acc[1][2], A1, w2); ffma2(acc[1][3], A1, w3);
                ffma2(acc[2][0], A2, w0); ffma2(acc[2][1], A2, w1);
                ffma2(acc[2][2], A2, w2); ffma2(acc[2][3], A2, w3);
                ffma2(acc[3][0], A3, w0); ffma2(acc[3][1], A3, w1);
                ffma2(acc[3][2], A3, w2); ffma2(acc[3][3], A3, w3);
                wp += 64;   // next k row (128 floats)
            }

            // ---- epilogue: bias + ELU + store ----
            #pragma unroll
            for (int r = 0; r < 4; r++) {
                int row = tile * TM + mrow + r;
                if (row < n) {
                    float o[8];
                    #pragma unroll
                    for (int c = 0; c < 4; c++) {
                        float2 q = upk(acc[r][c]);
                        o[2 * c]     = q.x + b[2 * c];
                        o[2 * c + 1] = q.y + b[2 * c + 1];
                    }
                    #pragma unroll
                    for (int j = 0; j < 8; j++) {
                        float v = o[j];
                        o[j] = (v > 0.f) ? v : expm1f(v);
                    }
                    float4* Yv = (float4*)(Y + (size_t)row * D + ncol);
                    Yv[0] = make_float4(o[0], o[1], o[2], o[3]);
                    Yv[1] = make_float4(o[4], o[5], o[6], o[7]);
                }
            }
        } else {
            int next = tile + gridDim.x;
            if (next < ntiles)
                produce_tile(nxt, X4, next, n, wid, lane);
        }

        __syncthreads();
        p ^= 1;
    }
}

// ---------------- launch ----------------
extern "C" void kernel_launch(void* const* d_in, const int* in_sizes, int n_in,
                              void* d_out, int out_size)
{
    const float* X0    = (const float*)d_in[0];   // node_embedding [N,128]
    const int*   ei    = (const int*)  d_in[1];   // edge_index [2,E]
    const float* Wrel  = (const float*)d_in[2];   // [L,128,128]
    const float* brel  = (const float*)d_in[3];   // [L,128]
    const float* Wroot = (const float*)d_in[4];   // [L,128,128]
    float* out = (float*)d_out;

    int n = in_sizes[0] / D;
    int e = in_sizes[1] / 2;
    int L = in_sizes[2] / (D * D);

    const int* src = ei;
    const int* dst = ei + e;

    // --- CSR build (dst-sorted adjacency); 5 launches ---
    zero_deg_kernel<<<(n + 255) / 256, 256>>>(n);
    count_kernel<<<(e + 255) / 256, 256>>>(dst, e);
    int nb = (n + 511) / 512;
    scan_block_kernel<<<nb, 512>>>(n);
    scan_add_spine_kernel<<<(n + 1 + 511) / 512, 512>>>(n, e, nb);
    fill_kernel<<<(e + 255) / 256, 256>>>(src, dst, e);

    cudaFuncSetAttribute(fused_layer_kernel,
                         cudaFuncAttributeMaxDynamicSharedMemorySize, FUSED_SMEM);

    int nsm = 148;
    {
        int dev = 0, v = 0;
        if (cudaGetDevice(&dev) == cudaSuccess &&
            cudaDeviceGetAttribute(&v, cudaDevAttrMultiProcessorCount, dev) == cudaSuccess &&
            v > 0) nsm = v;
    }

    int ntiles = (n + TM - 1) / TM;
    int grid   = (ntiles < nsm) ? ntiles : nsm;
    if (grid < 1) grid = 1;

    int xsel = 0;
    const float* xext = X0;
    for (int l = 0; l < L; l++) {
        int ysel;
        float* yext;
        if (l == L - 1) { ysel = 0; yext = out; }
        else            { ysel = (l & 1) ? 2 : 1; yext = out; /* unused */ }

        fused_layer_kernel<<<grid, NTHREADS, FUSED_SMEM>>>(
            xext, xsel,
            Wrel + (size_t)l * D * D,
            Wroot + (size_t)l * D * D,
            brel + (size_t)l * D,
            yext, ysel, n, ntiles);

        xsel = ysel;
        xext = yext;
    }
}

// round 15
// speedup vs baseline: 1.0657x; 1.0657x over previous
#include <cuda_runtime.h>
#include <math.h>

#define D 128
#define MAXN 50048
#define MAXE 600064
#define TM 64
#define GEMM_SMEM ((256*128 + 256*TM) * 4)   // 192 KB: W1|W2 + transposed [agg|X] tile

// ---------------- device scratch (no allocations allowed) ----------------
__device__ float g_agg [(size_t)MAXN * D];
__device__ float g_bufA[(size_t)MAXN * D];
__device__ float g_bufB[(size_t)MAXN * D];
__device__ int   g_deg[MAXN];
__device__ int   g_off[MAXN + 1];
__device__ int   g_cursor[MAXN];
__device__ int   g_csr[MAXE];
__device__ int   g_bsum[256];
__device__ float g_invdeg[MAXN];

// buffer selectors: 0 = external pointer, 1 = g_bufA, 2 = g_bufB
static __device__ __forceinline__ const float* sel_src(const float* ext, int s) {
    return (s == 0) ? ext : ((s == 1) ? g_bufA : g_bufB);
}
static __device__ __forceinline__ float* sel_dst(float* ext, int s) {
    return (s == 0) ? ext : ((s == 1) ? g_bufA : g_bufB);
}

// ---------------- packed f32x2 helpers (FFMA2: 2x fp32 FMA throughput) ----
static __device__ __forceinline__ unsigned long long pk2(float x) {
    unsigned long long r;
    asm("mov.b64 %0, {%1, %1};" : "=l"(r) : "f"(x));
    return r;
}
static __device__ __forceinline__ void ffma2(unsigned long long& d,
                                             unsigned long long a,
                                             unsigned long long b) {
    asm("fma.rn.f32x2 %0, %1, %2, %0;" : "+l"(d) : "l"(a), "l"(b));
}
static __device__ __forceinline__ float2 upk(unsigned long long v) {
    float2 r;
    asm("mov.b64 {%0, %1}, %2;" : "=f"(r.x), "=f"(r.y) : "l"(v));
    return r;
}

// ---------------- CSR build (5 launches; agg is launch #5) -----------------
__global__ void zero_deg_kernel(int n) {
    int i = blockIdx.x * blockDim.x + threadIdx.x;
    if (i < n) g_deg[i] = 0;
}

__global__ void count_kernel(const int* __restrict__ dst, int e) {
    int i = blockIdx.x * blockDim.x + threadIdx.x;
    if (i < e) atomicAdd(&g_deg[dst[i]], 1);
}

// per-512-block exclusive scan over degrees; also emits inv_deg = 1/max(deg,1)
__global__ void scan_block_kernel(int n) {
    __shared__ int s[512];
    int t = threadIdx.x;
    int i = blockIdx.x * 512 + t;
    int v = (i < n) ? g_deg[i] : 0;
    if (i < n) g_invdeg[i] = 1.0f / fmaxf((float)v, 1.0f);
    s[t] = v;
    __syncthreads();
    #pragma unroll
    for (int d = 1; d < 512; d <<= 1) {
        int x = (t >= d) ? s[t - d] : 0;
        __syncthreads();
        s[t] += x;
        __syncthreads();
    }
    if (i < n) g_off[i] = s[t] - v;
    if (t == 511) g_bsum[blockIdx.x] = s[511];
}

// merged spine-scan + add: every block redundantly scans the (<=128) block
// sums in smem, then applies the exclusive spine offset.
__global__ void scan_add_spine_kernel(int n, int e, int nb) {
    __shared__ int s[128];
    __shared__ int orig[128];
    int t = threadIdx.x;          // 512 threads
    if (t < 128) {
        int v = (t < nb) ? g_bsum[t] : 0;
        orig[t] = v;
        s[t] = v;
    }
    __syncthreads();
    #pragma unroll
    for (int d = 1; d < 128; d <<= 1) {
        int x = (t < 128 && t >= d) ? s[t - d] : 0;
        __syncthreads();
        if (t < 128) s[t] += x;
        __syncthreads();
    }
    int i = blockIdx.x * blockDim.x + t;
    if (i < n) {
        int o = g_off[i] + (s[i >> 9] - orig[i >> 9]);   // exclusive spine
        g_off[i] = o;
        g_cursor[i] = o;
    } else if (i == n) {
        g_off[n] = e;
    }
}

__global__ void fill_kernel(const int* __restrict__ src, const int* __restrict__ dst, int e) {
    int i = blockIdx.x * blockDim.x + threadIdx.x;
    if (i < e) {
        int d = dst[i];
        int p = atomicAdd(&g_cursor[d], 1);
        g_csr[p] = src[i];
    }
}

// ---------------- mean aggregation: 4 nodes per warp, interleaved ----------
// Each warp advances 4 nodes simultaneously: 16 float4 gathers (8 KB) in
// flight, next 16 CSR indices prefetched concurrently. Standalone kernel at
// full occupancy (no competing LDS stream on the SM).
__global__ __launch_bounds__(256) void agg_kernel(
    const float* __restrict__ Xext, int xsel, int n)
{
    const float4* X4 = (const float4*)sel_src(Xext, xsel);
    int warp = blockIdx.x * (blockDim.x >> 5) + (threadIdx.x >> 5);
    int lane = threadIdx.x & 31;
    int base = warp * 4;
    if (base >= n) return;

    int kk[4], ee[4];
    float4 acc[4];
    #pragma unroll
    for (int i = 0; i < 4; i++) {
        int row = base + i;
        if (row < n) {
            kk[i] = __ldg(&g_off[row]);
            ee[i] = __ldg(&g_off[row + 1]);
        } else {
            kk[i] = 0; ee[i] = 0;
        }
        acc[i] = make_float4(0.f, 0.f, 0.f, 0.f);
    }

    // current index group: 4 slots per node, -1 = invalid
    int jc[16];
    #pragma unroll
    for (int i = 0; i < 4; i++)
        #pragma unroll
        for (int s = 0; s < 4; s++) {
            int pos = kk[i] + s;
            jc[i * 4 + s] = (pos < ee[i]) ? __ldg(&g_csr[pos]) : -1;
        }

    for (;;) {
        int more = 0;
        #pragma unroll
        for (int i = 0; i < 4; i++) more |= (kk[i] + 4 < ee[i]);

        // prefetch next index group (overlaps the gathers below)
        int jn[16];
        #pragma unroll
        for (int i = 0; i < 4; i++)
            #pragma unroll
            for (int s = 0; s < 4; s++) {
                int pos = kk[i] + 4 + s;
                jn[i * 4 + s] = (more && pos < ee[i]) ? __ldg(&g_csr[pos]) : -1;
            }

        // 16 gathers in flight (4 nodes x 4 slots)
        #pragma unroll
        for (int i = 0; i < 4; i++)
            #pragma unroll
            for (int s = 0; s < 4; s++) {
                int jj = jc[i * 4 + s];
                if (jj >= 0) {
                    float4 v = __ldg(&X4[(size_t)jj * 32 + lane]);
                    acc[i].x += v.x; acc[i].y += v.y;
                    acc[i].z += v.z; acc[i].w += v.w;
                }
            }

        #pragma unroll
        for (int i = 0; i < 4; i++) kk[i] += 4;
        if (!more) break;
        #pragma unroll
        for (int s = 0; s < 16; s++) jc[s] = jn[s];
    }

    #pragma unroll
    for (int i = 0; i < 4; i++) {
        int row = base + i;
        if (row < n) {
            float sc = __ldg(&g_invdeg[row]);
            acc[i].x *= sc; acc[i].y *= sc; acc[i].z *= sc; acc[i].w *= sc;
            ((float4*)g_agg)[(size_t)row * 32 + lane] = acc[i];
        }
    }
}

// ---------------- persistent fused GEMM: Y = ELU( agg@W1 + X@W2 + b ) -----
// grid = #SMs, 1 CTA/SM, 256 threads. Weights in SMEM once; CTA loops over
// 64-row tiles, prefetching the next tile into registers during the FFMA2
// main loop and committing via conflict-free STS after a sync.
// (Proven kernel from the 475 us run — unchanged.)
__global__ __launch_bounds__(256, 1) void gemm_elu_kernel(
    const float* __restrict__ Xext, int xsel,
    const float* __restrict__ W1, const float* __restrict__ W2,
    const float* __restrict__ bias,
    float* __restrict__ Yext, int ysel, int n, int ntiles)
{
    extern __shared__ float smem[];
    float* sW  = smem;                // [256][128] : k<128 -> W1, else W2
    float* sIn = smem + 256 * 128;    // [256][TM]  : transposed [agg|X] tile

    const float* X = sel_src(Xext, xsel);
    float* Y = sel_dst(Yext, ysel);

    int t = threadIdx.x;
    int mrow = (t & 15) * 4;      // 4 rows
    int ncol = (t >> 4) * 8;      // 8 cols = 4 f32x2 pairs

    // ---- load weights ONCE ----
    {
        const float4* W1v = (const float4*)W1;
        const float4* W2v = (const float4*)W2;
        float4* sWv = (float4*)sW;
        #pragma unroll
        for (int i = 0; i < 16; i++) {
            int idx = t + i * 256;
            sWv[idx]        = __ldg(&W1v[idx]);
            sWv[idx + 4096] = __ldg(&W2v[idx]);
        }
    }

    float b[8];
    #pragma unroll
    for (int j = 0; j < 8; j++) b[j] = __ldg(&bias[ncol + j]);

    float4 pf[16];

    int tile = blockIdx.x;
    // ---- prologue: fetch first tile ----
    #pragma unroll
    for (int i = 0; i < 16; i++) {
        int idx = t + i * 256;
        int q   = idx >> 11;            // 0 = agg, 1 = X
        int rem = idx & 2047;
        int m   = rem & 63;             // lane-fastest -> conflict-free STS
        int kv  = rem >> 6;             // float4 column 0..31
        int row = tile * TM + m;
        float4 v = make_float4(0.f, 0.f, 0.f, 0.f);
        const float* srcp = q ? X : g_agg;
        if (tile < ntiles && row < n)
            v = __ldg(&((const float4*)srcp)[(size_t)row * 32 + kv]);
        pf[i] = v;
    }
    #pragma unroll
    for (int i = 0; i < 16; i++) {
        int idx = t + i * 256;
        int q   = idx >> 11;
        int rem = idx & 2047;
        int m   = rem & 63;
        int kv  = rem >> 6;
        int kb  = q * 128 + kv * 4;
        sIn[(kb + 0) * TM + m] = pf[i].x;
        sIn[(kb + 1) * TM + m] = pf[i].y;
        sIn[(kb + 2) * TM + m] = pf[i].z;
        sIn[(kb + 3) * TM + m] = pf[i].w;
    }
    __syncthreads();

    for (; tile < ntiles; tile += gridDim.x) {
        int next = tile + gridDim.x;

        // ---- issue prefetch LDGs for the NEXT tile (hidden under compute) --
        if (next < ntiles) {
            #pragma unroll
            for (int i = 0; i < 16; i++) {
                int idx = t + i * 256;
                int q   = idx >> 11;
                int rem = idx & 2047;
                int m   = rem & 63;
                int kv  = rem >> 6;
                int row = next * TM + m;
                float4 v = make_float4(0.f, 0.f, 0.f, 0.f);
                const float* srcp = q ? X : g_agg;
                if (row < n)
                    v = __ldg(&((const float4*)srcp)[(size_t)row * 32 + kv]);
                pf[i] = v;
            }
        }

        // ---- FFMA2 main loop over K=256 ----
        unsigned long long acc[4][4];
        #pragma unroll
        for (int r = 0; r < 4; r++)
            #pragma unroll
            for (int c = 0; c < 4; c++) acc[r][c] = 0ull;

        const float* aptr = sIn + mrow;
        const unsigned long long* wptr = (const unsigned long long*)(sW + ncol);

        #pragma unroll 4
        for (int k = 0; k < 256; k++) {
            float4 av = *(const float4*)aptr;
            unsigned long long a0 = pk2(av.x), a1 = pk2(av.y),
                               a2 = pk2(av.z), a3 = pk2(av.w);
            unsigned long long w0 = wptr[0], w1 = wptr[1],
                               w2 = wptr[2], w3 = wptr[3];
            ffma2(acc[0][0], a0, w0); ffma2(acc[0][1], a0, w1);
            ffma2(acc[0][2], a0, w2); ffma2(acc[0][3], a0, w3);
            ffma2(acc[1][0], a1, w0); ffma2(acc[1][1], a1, w1);
            ffma2(acc[1][2], a1, w2); ffma2(acc[1][3], a1, w3);
            ffma2(acc[2][0], a2, w0); ffma2(acc[2][1], a2, w1);
            ffma2(acc[2][2], a2, w2); ffma2(acc[2][3], a2, w3);
            ffma2(acc[3][0], a3, w0); ffma2(acc[3][1], a3, w1);
            ffma2(acc[3][2], a3, w2); ffma2(acc[3][3], a3, w3);
            aptr += TM;
            wptr += 64;   // 128 floats = 64 u64
        }

        // ---- epilogue: bias + ELU + store ----
        #pragma unroll
        for (int r = 0; r < 4; r++) {
            int row = tile * TM + mrow + r;
            if (row < n) {
                float o[8];
                #pragma unroll
                for (int c = 0; c < 4; c++) {
                    float2 p = upk(acc[r][c]);
                    o[2 * c]     = p.x + b[2 * c];
                    o[2 * c + 1] = p.y + b[2 * c + 1];
                }
                #pragma unroll
                for (int j = 0; j < 8; j++) {
                    float v = o[j];
                    o[j] = (v > 0.f) ? v : expm1f(v);
                }
                float4* Yv = (float4*)(Y + (size_t)row * D + ncol);
                Yv[0] = make_float4(o[0], o[1], o[2], o[3]);
                Yv[1] = make_float4(o[4], o[5], o[6], o[7]);
            }
        }

        __syncthreads();          // everyone done reading sIn
        if (next < ntiles) {
            #pragma unroll
            for (int i = 0; i < 16; i++) {
                int idx = t + i * 256;
                int q   = idx >> 11;
                int rem = idx & 2047;
                int m   = rem & 63;
                int kv  = rem >> 6;
                int kb  = q * 128 + kv * 4;
                sIn[(kb + 0) * TM + m] = pf[i].x;
                sIn[(kb + 1) * TM + m] = pf[i].y;
                sIn[(kb + 2) * TM + m] = pf[i].z;
                sIn[(kb + 3) * TM + m] = pf[i].w;
            }
        }
        __syncthreads();          // sIn committed for next tile
    }
}

// ---------------- launch ----------------
extern "C" void kernel_launch(void* const* d_in, const int* in_sizes, int n_in,
                              void* d_out, int out_size)
{
    const float* X0    = (const float*)d_in[0];   // node_embedding [N,128]
    const int*   ei    = (const int*)  d_in[1];   // edge_index [2,E]
    const float* Wrel  = (const float*)d_in[2];   // [L,128,128]
    const float* brel  = (const float*)d_in[3];   // [L,128]
    const float* Wroot = (const float*)d_in[4];   // [L,128,128]
    float* out = (float*)d_out;

    int n = in_sizes[0] / D;
    int e = in_sizes[1] / 2;
    int L = in_sizes[2] / (D * D);

    const int* src = ei;
    const int* dst = ei + e;

    // --- CSR build (dst-sorted adjacency); 5 launches ---
    zero_deg_kernel<<<(n + 255) / 256, 256>>>(n);
    count_kernel<<<(e + 255) / 256, 256>>>(dst, e);
    int nb = (n + 511) / 512;
    scan_block_kernel<<<nb, 512>>>(n);
    scan_add_spine_kernel<<<(n + 1 + 511) / 512, 512>>>(n, e, nb);
    fill_kernel<<<(e + 255) / 256, 256>>>(src, dst, e);

    cudaFuncSetAttribute(gemm_elu_kernel,
                         cudaFuncAttributeMaxDynamicSharedMemorySize, GEMM_SMEM);

    int nsm = 148;
    {
        int dev = 0, v = 0;
        if (cudaGetDevice(&dev) == cudaSuccess &&
            cudaDeviceGetAttribute(&v, cudaDevAttrMultiProcessorCount, dev) == cudaSuccess &&
            v > 0) nsm = v;
    }

    int agg_blocks = (n + 31) / 32;          // 8 warps/block, 4 nodes/warp
    int ntiles     = (n + TM - 1) / TM;
    int gemm_grid  = (ntiles < nsm) ? ntiles : nsm;
    if (gemm_grid < 1) gemm_grid = 1;

    int xsel = 0;
    const float* xext = X0;
    for (int l = 0; l < L; l++) {
        int ysel;
        float* yext;
        if (l == L - 1) { ysel = 0; yext = out; }
        else            { ysel = (l & 1) ? 2 : 1; yext = out; /* unused */ }

        agg_kernel<<<agg_blocks, 256>>>(xext, xsel, n);
        gemm_elu_kernel<<<gemm_grid, 256, GEMM_SMEM>>>(
            xext, xsel,
            Wrel + (size_t)l * D * D,
            Wroot + (size_t)l * D * D,
            brel + (size_t)l * D,
            yext, ysel, n, ntiles);

        xsel = ysel;
        xext = yext;
    }
}